// round 9
// baseline (speedup 1.0000x reference)
#include <cuda_runtime.h>

// ---------------------------------------------------------------------------
// ContrastiveCRFLoss — B200 (sm_100a), round 9.
//
// = round-8 (55.5us) minus the 5us prep/sort launch:
//   - gather uses identity sample order (R2 measured this exact mapping,
//     unsorted, at 63.4% DRAM — sort was never load-bearing)
//   - pair list is per-row (no atomics, no counter reset) -> 2 launches total
//   - sparse keeps warp-per-pair lane=batch coalesced shape, fed by row lists
//
// Exact-zero sparsity: out[n,a,b] != -0.0 only for integer pixel-dist^2
// cd <= 105 (~6k of 1M ordered pairs, batch independent).
// ---------------------------------------------------------------------------

#define NB     32
#define KC     27
#define NS     1000
#define HW     256
#define CD_MAX 105.0f
#define ROWCAP 64

#define PAIRB  4
#define GB     3375                  // gather blocks: 864000 threads
#define ZB     4096                  // zfill blocks:  1M threads x 8 float4
#define NBLK   (PAIRB + GB + ZB)     // 7475

// record table, transposed: d_recT[s][word][n], word 0..26=C, 27..29=G
__device__ float    d_recT[NS * 32 * NB];      // 4 MB
__device__ unsigned d_rowPair[NS * ROWCAP];    // packed (cd<<10 | b)
__device__ int      d_rowCnt[NS];

// ---------------------------------------------------------------------------
// k0: fused pairs + gather + zfill (contiguous roles)
// ---------------------------------------------------------------------------
__global__ void __launch_bounds__(256)
fused_k(const float* __restrict__ guidance,
        const float* __restrict__ clusters,
        const int*   __restrict__ coords,
        float4* __restrict__ out, int n4) {
    const int bid = blockIdx.x;
    const int tid = threadIdx.x;

    if (bid < PAIRB) {
        // ---- per-row pair enumeration: thread a scans all b (no atomics) ----
        __shared__ float sr[NS], sc[NS];
        for (int i = tid; i < NS; i += 256) {
            sr[i] = (float)__ldg(&coords[i]);
            sc[i] = (float)__ldg(&coords[NS + i]);
        }
        __syncthreads();

        int a = bid * 256 + tid;
        if (a < NS) {
            float arf = sr[a], acf = sc[a];
            int cnt = 0;
            unsigned* row = d_rowPair + a * ROWCAP;
            #pragma unroll 4
            for (int b = 0; b < NS; b++) {
                float dr = arf - sr[b];
                float dc = acf - sc[b];
                float cd = dr * dr + dc * dc;
                if (cd <= CD_MAX && cnt < ROWCAP) {
                    row[cnt] = ((unsigned)(int)cd << 10) | (unsigned)b;
                    cnt++;
                }
            }
            d_rowCnt[a] = cnt;
        }
    } else if (bid < PAIRB + GB) {
        // ---- gather (R2-measured mapping, identity order) ----
        int idx = (bid - PAIRB) * 256 + tid;       // < 864000 exactly
        int nk  = idx / NS;                        // n*27 + k
        int s   = idx - nk * NS;
        int n = nk / KC;
        int k = nk - n * KC;

        int r = __ldg(&coords[s]);
        int c = __ldg(&coords[NS + s]);
        int px = r * HW + c;

        float v = __ldg(&clusters[((size_t)nk * HW * HW) + px]);
        d_recT[((size_t)s * 32 + k) * NB + n] = v;

        if (k < 3) {
            float g = __ldg(&guidance[(((size_t)n * 3 + k) * HW * HW) + px]);
            d_recT[((size_t)s * 32 + 27 + k) * NB + n] = g;
        }
    } else {
        // ---- zero-fill output ----
        int zidx = (bid - PAIRB - GB) * 256 + tid; // [0, 1048576)
        float4 z = make_float4(0.f, 0.f, 0.f, 0.f);
        #pragma unroll
        for (int it = 0; it < 8; it++) {
            int i = zidx + it * (ZB * 256);
            if (i < n4) out[i] = z;
        }
    }
}

// ---------------------------------------------------------------------------
// k1: sparse compute — warp per (row, slot-stripe); lane = batch n.
// Warp g: a = g>>4, slots g&15, +16, ...  (16 stripes/row; typical cnt ~6)
// ---------------------------------------------------------------------------
__global__ void __launch_bounds__(256)
sparse_k(float* __restrict__ out) {
    const int gw    = (blockIdx.x * blockDim.x + threadIdx.x) >> 5;
    const int lane  = threadIdx.x & 31;
    const int a     = gw >> 4;
    const int slot0 = gw & 15;
    if (a >= NS) return;

    const int cnt = __ldg(&d_rowCnt[a]);
    if (slot0 >= cnt) return;

    // hoist A-side record: 30 coalesced 128B loads
    const float* raBase = d_recT + (size_t)a * 32 * NB + lane;
    float ra[30];
    #pragma unroll
    for (int w = 0; w < 30; w++) ra[w] = __ldg(raBase + w * NB);

    const unsigned* row = d_rowPair + a * ROWCAP;

    for (int slot = slot0; slot < cnt; slot += 16) {
        unsigned e = __ldg(&row[slot]);
        int   b  = (int)(e & 1023u);
        float cd = (float)(e >> 10);

        const float* rbBase = d_recT + (size_t)b * 32 * NB + lane;

        float dot = 0.f;
        #pragma unroll
        for (int k = 0; k < KC; k++)
            dot = fmaf(ra[k], __ldg(rbBase + k * NB), dot);

        float gd = 0.f;
        #pragma unroll
        for (int ch = 0; ch < 3; ch++) {
            float d = ra[27 + ch] - __ldg(rbBase + (27 + ch) * NB);
            gd = fmaf(d, d, gd);
        }

        float s1 = 10.0f * __expf(-cd - gd * 3.33333333f);
        float s2 = 3.0f  * __expf(-10.0f * cd);

        out[((size_t)lane * NS + a) * NS + b] = -dot * (s1 + s2);
    }
}

// ---------------------------------------------------------------------------
extern "C" void kernel_launch(void* const* d_in, const int* in_sizes, int n_in,
                              void* d_out, int out_size) {
    const float* guidance = (const float*)d_in[0];
    const float* clusters = (const float*)d_in[1];
    const int*   coords   = (const int*)d_in[2];
    float* out = (float*)d_out;

    fused_k<<<NBLK, 256>>>(guidance, clusters, coords,
                           (float4*)out, out_size / 4);
    sparse_k<<<(NS * 16) / 8, 256>>>(out);   // 16000 warps
}

// round 10
// speedup vs baseline: 1.3067x; 1.3067x over previous
#include <cuda_runtime.h>

// ---------------------------------------------------------------------------
// ContrastiveCRFLoss — B200 (sm_100a), round 10.
//
// = round-8 (55.5us best) with the 5us standalone sort launch hidden:
//   L1 pz_k    : bid 0          counting sort (256-thread version)
//                bid 1..4096    zero-fill 128MB output      (verbatim R8)
//                bid 4097..     pair enumeration, atomics   (verbatim R8)
//   L2 gather_k: sorted gather (verbatim R8 fused gather branch)
//   L3 sparse_k: warp-per-pair lane=batch (verbatim R8) + last-block reset
//                of d_npairs/d_done for the next graph replay.
//
// Exact-zero sparsity: out[n,a,b] != -0.0 only for integer pixel-dist^2
// cd <= 105 (~6k of 1M ordered pairs, batch independent).
// ---------------------------------------------------------------------------

#define NB    32
#define KC    27
#define NS    1000
#define HW    256
#define MAXP  32768
#define CD_MAX 105.0f

#define ZB    4096                 // zfill blocks
#define PB    4096                 // pair blocks
#define GB    3375                 // gather blocks

// record table, transposed: d_recT[s][word][n], word 0..26=C, 27..29=G
__device__ float    d_recT[NS * 32 * NB];     // 4 MB
__device__ int      d_order[1024];            // spatially sorted sample ids
__device__ unsigned d_pairs[MAXP];            // (a<<10)|b
__device__ float    d_pcd[MAXP];              // cd per pair
__device__ int      d_npairs;                 // reset by sparse_k tail
__device__ int      d_done;                   // sparse_k completion counter

// ---------------------------------------------------------------------------
// L1: sort (bid 0) + zfill + pairs
// ---------------------------------------------------------------------------
__global__ void __launch_bounds__(256)
pz_k(const int* __restrict__ coords, float4* __restrict__ out, int n4) {
    const int bid = blockIdx.x;
    const int tid = threadIdx.x;

    if (bid == 0) {
        // ---- counting sort by spatial bin (px >> 6), 256 threads ----
        __shared__ int hist[1024];
        __shared__ int base[1024];
        __shared__ int wsum[8];
        __shared__ short sbin[NS];
        __shared__ short srank[NS];

        #pragma unroll
        for (int q = 0; q < 4; q++) hist[q * 256 + tid] = 0;
        __syncthreads();

        #pragma unroll
        for (int q = 0; q < 4; q++) {
            int i = q * 256 + tid;
            if (i < NS) {
                int r = __ldg(&coords[i]);
                int c = __ldg(&coords[NS + i]);
                int bin = (r * 256 + c) >> 6;              // 0..1023
                sbin[i]  = (short)bin;
                srank[i] = (short)atomicAdd(&hist[bin], 1);
            }
        }
        __syncthreads();

        // scan: thread t owns bins 4t..4t+3
        int h0 = hist[4 * tid + 0], h1 = hist[4 * tid + 1];
        int h2 = hist[4 * tid + 2], h3 = hist[4 * tid + 3];
        int tsum = h0 + h1 + h2 + h3;

        const int lane = tid & 31, w = tid >> 5;
        int v = tsum;
        #pragma unroll
        for (int o = 1; o < 32; o <<= 1) {
            int t = __shfl_up_sync(0xffffffffu, v, o);
            if (lane >= o) v += t;                          // inclusive
        }
        if (lane == 31) wsum[w] = v;
        __syncthreads();
        if (tid < 8) {
            int s = wsum[tid];
            #pragma unroll
            for (int o = 1; o < 8; o <<= 1) {
                int t = __shfl_up_sync(0xffu, s, o);
                if (tid >= o) s += t;
            }
            wsum[tid] = s;
        }
        __syncthreads();
        int excl = ((w == 0) ? 0 : wsum[w - 1]) + v - tsum;
        base[4 * tid + 0] = excl;
        base[4 * tid + 1] = excl + h0;
        base[4 * tid + 2] = excl + h0 + h1;
        base[4 * tid + 3] = excl + h0 + h1 + h2;
        __syncthreads();

        #pragma unroll
        for (int q = 0; q < 4; q++) {
            int i = q * 256 + tid;
            if (i < NS)
                d_order[base[sbin[i]] + srank[i]] = i;
        }
    } else if (bid <= ZB) {
        // ---- zero-fill output (verbatim R8) ----
        int zidx = (bid - 1) * 256 + tid;                  // [0, 1048576)
        float4 z = make_float4(0.f, 0.f, 0.f, 0.f);
        #pragma unroll
        for (int it = 0; it < 8; it++) {
            int i = zidx + it * (ZB * 256);
            if (i < n4) out[i] = z;
        }
    } else {
        // ---- pair enumeration (verbatim R8; d_npairs reset by prev sparse) ----
        int idx = (bid - 1 - ZB) * 256 + tid;              // [0, 1048576)
        int a = idx >> 10;
        int b = idx & 1023;
        if (a < NS && b < NS) {
            float dr = (float)(__ldg(&coords[a])      - __ldg(&coords[b]));
            float dc = (float)(__ldg(&coords[NS + a]) - __ldg(&coords[NS + b]));
            float cd = dr * dr + dc * dc;
            if (cd <= CD_MAX) {
                int pos = atomicAdd(&d_npairs, 1);
                if (pos < MAXP) {
                    d_pairs[pos] = ((unsigned)a << 10) | (unsigned)b;
                    d_pcd[pos]   = cd;
                }
            }
        }
    }
}

// ---------------------------------------------------------------------------
// L2: sorted gather (verbatim R8 fused gather branch)
// ---------------------------------------------------------------------------
__global__ void __launch_bounds__(256)
gather_k(const float* __restrict__ guidance,
         const float* __restrict__ clusters,
         const int*   __restrict__ coords) {
    int idx = blockIdx.x * 256 + threadIdx.x;      // < 864000 exactly
    int nk   = idx / NS;                           // n*27 + k
    int sIdx = idx - nk * NS;
    int n = nk / KC;
    int k = nk - n * KC;

    int s = d_order[sIdx];
    int r = __ldg(&coords[s]);
    int c = __ldg(&coords[NS + s]);
    int px = r * HW + c;

    float v = __ldg(&clusters[((size_t)nk * HW * HW) + px]);
    d_recT[((size_t)s * 32 + k) * NB + n] = v;

    if (k < 3) {
        float g = __ldg(&guidance[(((size_t)n * 3 + k) * HW * HW) + px]);
        d_recT[((size_t)s * 32 + 27 + k) * NB + n] = g;
    }
}

// ---------------------------------------------------------------------------
// L3: sparse compute (verbatim R8) + counter reset for next replay
// ---------------------------------------------------------------------------
__global__ void __launch_bounds__(256)
sparse_k(float* __restrict__ out) {
    int gw   = (blockIdx.x * blockDim.x + threadIdx.x) >> 5;
    int lane = threadIdx.x & 31;

    int np = d_npairs;
    if (np > MAXP) np = MAXP;

    if (gw < np) {
        unsigned pr = d_pairs[gw];
        int a = (int)(pr >> 10);
        int b = (int)(pr & 1023u);
        float cd = d_pcd[gw];

        const float* ra = d_recT + (size_t)a * 32 * NB + lane;
        const float* rb = d_recT + (size_t)b * 32 * NB + lane;

        float dot = 0.f;
        #pragma unroll
        for (int k = 0; k < KC; k++)
            dot = fmaf(__ldg(ra + k * NB), __ldg(rb + k * NB), dot);

        float gd = 0.f;
        #pragma unroll
        for (int ch = 0; ch < 3; ch++) {
            float d = __ldg(ra + (27 + ch) * NB) - __ldg(rb + (27 + ch) * NB);
            gd = fmaf(d, d, gd);
        }

        float s1 = 10.0f * __expf(-cd - gd * 3.33333333f);
        float s2 = 3.0f  * __expf(-10.0f * cd);

        out[((size_t)lane * NS + a) * NS + b] = -dot * (s1 + s2);
    }

    // ---- last-block-done reset of d_npairs/d_done for the next replay.
    // Every thread's d_npairs read precedes its block's barrier, and the
    // reset fires only after ALL blocks arrive, so no read can see it.
    __syncthreads();
    if (threadIdx.x == 0) {
        int t = atomicAdd(&d_done, 1);
        if (t == (int)gridDim.x - 1) {
            d_npairs = 0;
            d_done   = 0;
        }
    }
}

// ---------------------------------------------------------------------------
extern "C" void kernel_launch(void* const* d_in, const int* in_sizes, int n_in,
                              void* d_out, int out_size) {
    const float* guidance = (const float*)d_in[0];
    const float* clusters = (const float*)d_in[1];
    const int*   coords   = (const int*)d_in[2];
    float* out = (float*)d_out;

    pz_k<<<1 + ZB + PB, 256>>>(coords, (float4*)out, out_size / 4);
    gather_k<<<GB, 256>>>(guidance, clusters, coords);
    sparse_k<<<MAXP / 8, 256>>>(out);
}